// round 10
// baseline (speedup 1.0000x reference)
#include <cuda_runtime.h>
#include <cuda_fp16.h>
#include <math.h>
#include <stdint.h>

// ---------------------------------------------------------------------------
// 2-layer LSTM, T=512, B=64, H=512, fp32 in/out.
// R10: (1) pre-pass kernel computes PG[t][b][2048] = x(t).Wx0^T + bias0
// time-parallel (no recurrence). (2) persistent kernel per interval t does
// only the recurrent GEMMs, rebalanced 3 phases/group:
//   A (warps 0-7, accum L1):  h0_0.Wx1, h0_1.Wx1, h1_0.Wh1  -> GB1A
//   B (warps 8-15): h0_0.Wh0, h0_1.Wh0 [store GB0, zero] , h1_1.Wh1 -> GB1B
// h0 chunks staged once jointly; h1 halves per-group. Concurrent updates:
// A threads -> h1(t) (+out), B threads -> h0(t+1) (GB0*SCL + PG[t+1]).
// fp16 2-term weights (x256, hi/lo), fp32 accum. 1 grid bar/step.
// ---------------------------------------------------------------------------

#define T_LEN 512
#define BSZ   64
#define HID   512
#define NCTA  128
#define NTHR  512

// shared chunk buffers: 4 x (32 rows x 1040B)
#define CHUNKB  33280u
#define BUF(i)  ((uint32_t)(i)*CHUNKB)
// main-kernel partials (float indices)
#define GB0F    33280u               // [8ks][16c][68]
#define GB1AF   41984u               // [8ks][16c][68]
#define GB1BF   50688u               // [8ks][16c][34] (b>=32 half)
#define BSF1    55040u               // 16 layer-1 biases
#define SMEM_MAIN (55040u*4u + 128u) // 220,288 B
// prepass partials
#define GBPF    33280u               // [16ks][16c][68]
#define BSPF    50688u               // 16 layer-0 biases
#define SMEM_PRE  (50688u*4u + 128u) // 202,880 B

#define SCL 0.00390625f              // 1/256 (weights prescaled x256)

// persistent scratch
__device__ __half g_xh[(size_t)T_LEN*BSZ*HID];
__device__ float  g_pg[(size_t)T_LEN*BSZ*2048];   // 256 MB precomputed gates
__device__ __half g_h0h[3][BSZ*HID];
__device__ __half g_h1h[3][BSZ*HID];
__device__ unsigned g_cnt;
__device__ unsigned g_gen;

__device__ __forceinline__ float sigm(float x) { return 1.0f / (1.0f + expf(-x)); }

__device__ __forceinline__ void cp16s(uint32_t dst, const void* src) {
    asm volatile("cp.async.cg.shared.global [%0], [%1], 16;" :: "r"(dst), "l"(src));
}
__device__ __forceinline__ void ldsm_x4(uint32_t addr, uint32_t r[4]) {
    asm volatile("ldmatrix.sync.aligned.m8n8.x4.shared.b16 {%0,%1,%2,%3}, [%4];"
        : "=r"(r[0]), "=r"(r[1]), "=r"(r[2]), "=r"(r[3]) : "r"(addr));
}
__device__ __forceinline__ void mma16816(float d[4], const uint32_t a[4],
                                         const uint32_t b[2]) {
    asm volatile("mma.sync.aligned.m16n8k16.row.col.f32.f16.f16.f32 "
        "{%0,%1,%2,%3}, {%4,%5,%6,%7}, {%8,%9}, {%0,%1,%2,%3};"
        : "+f"(d[0]), "+f"(d[1]), "+f"(d[2]), "+f"(d[3])
        : "r"(a[0]), "r"(a[1]), "r"(a[2]), "r"(a[3]), "r"(b[0]), "r"(b[1]));
}
#define CPWAIT(n)  asm volatile("cp.async.wait_group %0;" :: "n"(n) : "memory")
#define CPCOMMIT() asm volatile("cp.async.commit_group;" ::: "memory")
__device__ __forceinline__ void barg(int id) {
    asm volatile("bar.sync %0, 256;" :: "r"(id) : "memory");
}

// Grid-wide barrier (proven since R1). All 128 CTAs co-resident.
__device__ __forceinline__ void grid_bar() {
    __threadfence();
    __syncthreads();
    if (threadIdx.x == 0) {
        volatile unsigned* vg = &g_gen;
        unsigned g = *vg;
        unsigned t = atomicAdd(&g_cnt, 1u);
        if (t == NCTA - 1) {
            atomicExch(&g_cnt, 0u);
            __threadfence();
            atomicAdd(&g_gen, 1u);
        } else {
            while (*vg == g) { }
        }
        __threadfence();
    }
    __syncthreads();
}

// stage a 32-row x 512-k fp16 block; src32 = base of the 32-row block
__device__ __forceinline__ void stage_joint(uint32_t smb, uint32_t bufo,
    const __half* __restrict__ src32, int tid) {
    #pragma unroll
    for (int jj = 0; jj < 4; jj++) {
        int u = tid + jj * 512;
        int b = u >> 6, seg = u & 63;
        cp16s(smb + bufo + (uint32_t)(b * 1040 + seg * 16),
              src32 + (size_t)b * 512 + seg * 8);
    }
    CPCOMMIT();
}
__device__ __forceinline__ void stage_group(uint32_t smb, uint32_t bufo,
    const __half* __restrict__ src32, int gtid) {
    #pragma unroll
    for (int jj = 0; jj < 8; jj++) {
        int u = gtid + jj * 256;
        int b = u >> 6, seg = u & 63;
        cp16s(smb + bufo + (uint32_t)(b * 1040 + seg * 16),
              src32 + (size_t)b * 512 + seg * 8);
    }
    CPCOMMIT();
}

// 64k-window 2-term mma over one chunk (as R9)
__device__ __forceinline__ void chunk_mma(uint32_t smb, uint32_t bufo, int half_,
    const uint32_t wfm[2][4][4], uint32_t blane, int myks, float d[8][4])
{
    #pragma unroll
    for (int pair = 0; pair < 2; pair++) {
        #pragma unroll
        for (int kb = 0; kb < 4; kb++) {
            uint32_t addr = smb + bufo + (uint32_t)(pair * 16640) + blane
                          + (uint32_t)(myks * 128 + kb * 32);
            uint32_t b4[4];
            ldsm_x4(addr, b4);
            int nt = half_ * 4 + pair * 2;
            mma16816(d[nt],     wfm[0][kb], b4);
            mma16816(d[nt],     wfm[1][kb], b4);
            mma16816(d[nt + 1], wfm[0][kb], b4 + 2);
            mma16816(d[nt + 1], wfm[1][kb], b4 + 2);
        }
    }
}

__device__ __forceinline__ void store_full(float* smf, uint32_t gbF,
    int myks, int lane, const float d[8][4])
{
    float* gb0 = smf + gbF + myks * 1088 + (lane >> 2) * 68 + 2 * (lane & 3);
    #pragma unroll
    for (int nt = 0; nt < 8; nt++) {
        *(float2*)(gb0 + nt * 8)          = make_float2(d[nt][0], d[nt][1]);
        *(float2*)(gb0 + 8 * 68 + nt * 8) = make_float2(d[nt][2], d[nt][3]);
    }
}
__device__ __forceinline__ void store_half_hi(float* smf, uint32_t gbF,
    int myks, int lane, const float d[8][4])   // nt 4..7 only (b 32-63)
{
    float* gb0 = smf + gbF + myks * 544 + (lane >> 2) * 34 + 2 * (lane & 3);
    #pragma unroll
    for (int nt = 4; nt < 8; nt++) {
        *(float2*)(gb0 + (nt - 4) * 8)          = make_float2(d[nt][0], d[nt][1]);
        *(float2*)(gb0 + 8 * 34 + (nt - 4) * 8) = make_float2(d[nt][2], d[nt][3]);
    }
}

__global__ void convert_x(const float* __restrict__ x) {
    size_t i = (size_t)blockIdx.x * blockDim.x + threadIdx.x;   // float4 idx
    float4 v = reinterpret_cast<const float4*>(x)[i];
    __half2* p = reinterpret_cast<__half2*>(g_xh);
    p[2 * i]     = __floats2half2_rn(v.x, v.y);
    p[2 * i + 1] = __floats2half2_rn(v.z, v.w);
}

// ---------------- pre-pass: PG[t][b][2048] = x(t).Wx0^T + bias0 ----------------
__global__ void __launch_bounds__(NTHR, 1) xw0_prepass(
    const float* __restrict__ Wxh, const float* __restrict__ bxh,
    const float* __restrict__ bhh)
{
    extern __shared__ float smf[];
    char* smc = (char*)smf;
    const uint32_t smb = (uint32_t)__cvta_generic_to_shared(smf);
    const int tid = threadIdx.x;
    const int bj  = blockIdx.x;
    const int wid = tid >> 5, lane = tid & 31;

    const uint32_t wloff = (uint32_t)(((lane & 7) + ((lane >> 3) & 1) * 8) * 1040
                                     + ((lane >> 4) & 1) * 16);
    const uint32_t blane = (uint32_t)((((lane >> 4) & 1) * 8 + (lane & 7)) * 1040
                                     + ((lane >> 3) & 1) * 16);

    // layer-0 Wx tiles x256 hi/lo -> frags (32k window per warp)
    for (int idx = tid; idx < 8192; idx += NTHR) {
        int c = idx >> 9, k = idx & 511;
        float w = 256.0f * Wxh[((size_t)(c >> 2) * 512 + bj * 4 + (c & 3)) * 512 + k];
        __half hi = __float2half(w);
        __half lo = __float2half(w - __half2float(hi));
        *(__half*)(smc + 0 * 16640 + c * 1040 + k * 2) = hi;
        *(__half*)(smc + 1 * 16640 + c * 1040 + k * 2) = lo;
    }
    __syncthreads();
    uint32_t wfp[2][2][4];
    #pragma unroll
    for (int p = 0; p < 2; p++)
        #pragma unroll
        for (int kb = 0; kb < 2; kb++)
            ldsm_x4(smb + (uint32_t)(p * 16640) + wloff
                    + (uint32_t)((wid * 32 + kb * 16) * 2), wfp[p][kb]);
    __syncthreads();
    if (tid < 16) {
        int n = (tid >> 2) * 512 + bj * 4 + (tid & 3);
        smf[BSPF + tid] = bxh[n] + bhh[n];
    }

    float d[8][4];
    #pragma unroll
    for (int nt = 0; nt < 8; nt++)
        d[nt][0] = d[nt][1] = d[nt][2] = d[nt][3] = 0.f;

    // chunks q: t=q>>1, half=q&1; prefetch 3
    #pragma unroll
    for (int q = 0; q < 3; q++)
        stage_joint(smb, BUF(q), g_xh + (size_t)(q >> 1) * 32768 + (q & 1) * 16384, tid);

    for (int q = 0; q < 1024; q++) {
        CPWAIT(2); __syncthreads();
        if (q + 3 < 1024)
            stage_joint(smb, BUF((q + 3) & 3),
                        g_xh + (size_t)((q + 3) >> 1) * 32768 + ((q + 3) & 1) * 16384, tid);
        {
            int half_ = q & 1;
            #pragma unroll
            for (int pair = 0; pair < 2; pair++) {
                #pragma unroll
                for (int kb = 0; kb < 2; kb++) {
                    uint32_t addr = smb + BUF(q & 3) + (uint32_t)(pair * 16640)
                                  + blane + (uint32_t)(wid * 64 + kb * 32);
                    uint32_t b4[4];
                    ldsm_x4(addr, b4);
                    int nt = half_ * 4 + pair * 2;
                    mma16816(d[nt],     wfp[0][kb], b4);
                    mma16816(d[nt],     wfp[1][kb], b4);
                    mma16816(d[nt + 1], wfp[0][kb], b4 + 2);
                    mma16816(d[nt + 1], wfp[1][kb], b4 + 2);
                }
            }
        }
        if (q & 1) {
            store_full(smf, GBPF, wid, lane, d);   // 16 slots (wid 0..15)
            __syncthreads();
            int t = q >> 1;
            int vi = tid * 2, b = vi >> 4, gi = vi & 15;
            float s0 = 0.f, s1 = 0.f;
            #pragma unroll
            for (int ks = 0; ks < 16; ks++) {
                s0 += smf[GBPF + ks * 1088 + gi * 68 + b];
                s1 += smf[GBPF + ks * 1088 + (gi + 1) * 68 + b];
            }
            float2 v = make_float2(s0 * SCL + smf[BSPF + gi],
                                   s1 * SCL + smf[BSPF + gi + 1]);
            *(float2*)&g_pg[(size_t)t * 131072 + b * 2048
                            + (gi >> 2) * 512 + bj * 4 + (gi & 3)] = v;
            #pragma unroll
            for (int nt = 0; nt < 8; nt++)
                d[nt][0] = d[nt][1] = d[nt][2] = d[nt][3] = 0.f;
        }
    }
}

// ---------------- main persistent kernel ----------------
__global__ void __launch_bounds__(NTHR, 1) lstm_persistent(
    const float* __restrict__ Wxh, const float* __restrict__ Whh,
    const float* __restrict__ bxh, const float* __restrict__ bhh,
    float* __restrict__ out)
{
    extern __shared__ float smf[];
    char* smc = (char*)smf;
    const uint32_t smb = (uint32_t)__cvta_generic_to_shared(smf);
    const int tid = threadIdx.x;
    const int bj  = blockIdx.x;

    const int wid = tid >> 5, lane = tid & 31, gtid = tid & 255;
    const bool isA = (wid < 8);
    const int myks = isA ? wid : wid - 8;
    const int barid = isA ? 1 : 2;

    const uint32_t wloff = (uint32_t)(((lane & 7) + ((lane >> 3) & 1) * 8) * 1040
                                     + ((lane >> 4) & 1) * 16);
    const uint32_t blane = (uint32_t)((((lane >> 4) & 1) * 8 + (lane & 7)) * 1040
                                     + ((lane >> 3) & 1) * 16);

    uint32_t wf[2][2][4][4];   // A: [0]=Wx1,[1]=Wh1 ; B: [0]=Wh0,[1]=Wh1

    for (int l = 0; l < 2; l++) {
        for (int idx = tid; idx < 16384; idx += NTHR) {
            int m = idx >> 13, rem = idx & 8191, c = rem >> 9, k = rem & 511;
            const float* bp = m ? Whh : Wxh;
            float w = 256.0f * bp[((size_t)l * 2048 + (size_t)(c >> 2) * 512
                                 + bj * 4 + (c & 3)) * 512 + k];
            __half hi = __float2half(w);
            __half lo = __float2half(w - __half2float(hi));
            *(__half*)(smc + (m * 2 + 0) * 16640 + c * 1040 + k * 2) = hi;
            *(__half*)(smc + (m * 2 + 1) * 16640 + c * 1040 + k * 2) = lo;
        }
        __syncthreads();
        #pragma unroll
        for (int p = 0; p < 2; p++)
            #pragma unroll
            for (int kb = 0; kb < 4; kb++) {
                uint32_t ko = wloff + (uint32_t)((myks * 64 + kb * 16) * 2);
                if (l == 0 && !isA)
                    ldsm_x4(smb + (uint32_t)((2 + p) * 16640) + ko, wf[0][p][kb]);
                if (l == 1 && isA) {
                    ldsm_x4(smb + (uint32_t)((0 + p) * 16640) + ko, wf[0][p][kb]);
                    ldsm_x4(smb + (uint32_t)((2 + p) * 16640) + ko, wf[1][p][kb]);
                }
                if (l == 1 && !isA)
                    ldsm_x4(smb + (uint32_t)((2 + p) * 16640) + ko, wf[1][p][kb]);
            }
        __syncthreads();
    }
    if (tid < 16) {
        int n = (tid >> 2) * 512 + bj * 4 + (tid & 3);
        smf[BSF1 + tid] = bxh[2048 + n] + bhh[2048 + n];
    }
    if (tid < 256)   // zero h1 slot 2 (read at t=0)
        g_h1h[2][bj * 256 + tid] = __float2half(0.f);

    const int ub = gtid >> 2, ucc = tid & 3;
    const int col = bj * 4 + ucc;
    const int hidx = ub * HID + col;
    float c0r = 0.f, c1r = 0.f, h0last = 0.f, h1last = 0.f;
    float d[8][4];

    // prologue: h0(0) directly from PG[0] (h(-1)=0 => no recurrent term)
    if (!isA) {
        float gate[4];
        #pragma unroll
        for (int g = 0; g < 4; g++)
            gate[g] = g_pg[(size_t)ub * 2048 + g * 512 + col];
        float ig = sigm(gate[0]), fg = sigm(gate[1]);
        float gg = tanhf(gate[2]), og = sigm(gate[3]);
        c0r = ig * gg * 1.0f + fg * 0.f;
        c0r = fg * 0.f + ig * gg;
        h0last = og * tanhf(c0r);
        g_h0h[0][hidx] = __float2half(h0last);
    }
    grid_bar();

    for (int t = 0; t < T_LEN; t++) {
        const int s_h0r = t % 3, s_h1r = (t + 2) % 3;
        const int s_h0w = (t + 1) % 3, s_h1w = t % 3;

        #pragma unroll
        for (int nt = 0; nt < 8; nt++)
            d[nt][0] = d[nt][1] = d[nt][2] = d[nt][3] = 0.f;

        const __half* h0b = g_h0h[s_h0r];
        const __half* h1b = g_h1h[s_h1r] + (isA ? 0 : 32 * 512);

        stage_joint(smb, BUF(0), h0b, tid);
        stage_joint(smb, BUF(1), h0b + 32 * 512, tid);
        if (isA) stage_group(smb, BUF(2), h1b, gtid);
        else     stage_group(smb, BUF(3), h1b, gtid);

        // phase 0: h0_0
        CPWAIT(2); __syncthreads();
        chunk_mma(smb, BUF(0), 0, wf[0], blane, myks, d);
        // phase 1: h0_1
        CPWAIT(1); __syncthreads();
        chunk_mma(smb, BUF(1), 1, wf[0], blane, myks, d);
        if (!isA) {
            store_full(smf, GB0F, myks, lane, d);
            #pragma unroll
            for (int nt = 0; nt < 8; nt++)
                d[nt][0] = d[nt][1] = d[nt][2] = d[nt][3] = 0.f;
        }
        // phase 2: h1 half
        CPWAIT(0); barg(barid);
        if (isA) {
            chunk_mma(smb, BUF(2), 0, wf[1], blane, myks, d);
            store_full(smf, GB1AF, myks, lane, d);
        } else {
            chunk_mma(smb, BUF(3), 1, wf[1], blane, myks, d);
            store_half_hi(smf, GB1BF, myks, lane, d);
        }
        __syncthreads();

        // concurrent updates
        if (isA) {
            float gate[4];
            #pragma unroll
            for (int g = 0; g < 4; g++) {
                const float* q = smf + GB1AF + (g * 4 + ucc) * 68 + ub;
                float s = 0.f;
                #pragma unroll
                for (int sI = 0; sI < 8; sI++) s += q[sI * 1088];
                if (ub >= 32) {
                    const float* qb = smf + GB1BF + (g * 4 + ucc) * 34 + (ub - 32);
                    #pragma unroll
                    for (int sI = 0; sI < 8; sI++) s += qb[sI * 544];
                }
                gate[g] = s * SCL + smf[BSF1 + g * 4 + ucc];
            }
            float ig = sigm(gate[0]), fg = sigm(gate[1]);
            float gg = tanhf(gate[2]), og = sigm(gate[3]);
            c1r = fg * c1r + ig * gg;
            h1last = og * tanhf(c1r);
            g_h1h[s_h1w][hidx] = __float2half(h1last);
            out[(size_t)t * (BSZ * HID) + hidx] = h1last;
        } else if (t < T_LEN - 1) {
            float gate[4];
            const float* pg = g_pg + (size_t)(t + 1) * 131072 + (size_t)ub * 2048;
            #pragma unroll
            for (int g = 0; g < 4; g++) {
                const float* q = smf + GB0F + (g * 4 + ucc) * 68 + ub;
                float s = 0.f;
                #pragma unroll
                for (int sI = 0; sI < 8; sI++) s += q[sI * 1088];
                gate[g] = s * SCL + pg[g * 512 + col];
            }
            float ig = sigm(gate[0]), fg = sigm(gate[1]);
            float gg = tanhf(gate[2]), og = sigm(gate[3]);
            c0r = fg * c0r + ig * gg;
            h0last = og * tanhf(c0r);
            g_h0h[s_h0w][hidx] = __float2half(h0last);
        }
        grid_bar();
    }
    CPWAIT(0);

    // epilogue: each group writes its own states
    {
        const size_t OFF = (size_t)T_LEN * BSZ * HID;
        if (!isA) {
            out[OFF +         hidx] = h0last;
            out[OFF + 65536 + hidx] = c0r;
        } else {
            out[OFF + 32768 + hidx] = h1last;
            out[OFF + 98304 + hidx] = c1r;
        }
    }
}

extern "C" void kernel_launch(void* const* d_in, const int* in_sizes, int n_in,
                              void* d_out, int out_size) {
    const float* x   = (const float*)d_in[0];
    const float* Wxh = (const float*)d_in[1];
    const float* Whh = (const float*)d_in[2];
    const float* bxh = (const float*)d_in[3];
    const float* bhh = (const float*)d_in[4];
    float* out = (float*)d_out;

    convert_x<<<(T_LEN * BSZ * HID / 4) / 256, 256>>>(x);

    cudaFuncSetAttribute(xw0_prepass,
                         cudaFuncAttributeMaxDynamicSharedMemorySize, SMEM_PRE);
    xw0_prepass<<<NCTA, NTHR, SMEM_PRE>>>(Wxh, bxh, bhh);

    cudaFuncSetAttribute(lstm_persistent,
                         cudaFuncAttributeMaxDynamicSharedMemorySize, SMEM_MAIN);
    lstm_persistent<<<NCTA, NTHR, SMEM_MAIN>>>(Wxh, Whh, bxh, bhh, out);
}

// round 11
// speedup vs baseline: 1.3267x; 1.3267x over previous
#include <cuda_runtime.h>
#include <cuda_fp16.h>
#include <math.h>
#include <stdint.h>

// ---------------------------------------------------------------------------
// 2-layer LSTM, T=512, B=64, H=512, fp32 in/out. Persistent, 128 CTAs x 512.
// R11 (base = R9, best): all-upfront staging, ZERO mid-interval named bars.
// Interval t: stage h0(t) pair + h1(t-1) pair (x(t+1) pre-staged last
// interval). Two phases only:
//   wait(x+h0): A (warps 0-7): h0.Wx1 x2 | B (warps 8-15): x.Wx0 x2
//   wait(all) : A: h1.Wh1 x2            | B: h0.Wh0 x2
// x buffers ALIAS the GB partials region (x consumed in phase 1; partials
// stored post-sync; x(t+2) staged after update's GB reads). Concurrent
// updates: A->h1(t)+out, B->h0(t+1). fp16 2-term weights (x256 hi/lo),
// fp32 accum, /256 at update. 3-slot h rotation, 1 grid bar/step.
// ---------------------------------------------------------------------------

#define T_LEN 512
#define BSZ   64
#define HID   512
#define NCTA  128
#define NTHR  512

// smem byte layout
#define CHUNKB  33280u
// h chunks: [0]=h0_0 [1]=h0_1 [2]=h1_0 [3]=h1_1
#define HB(i)   ((uint32_t)(i)*CHUNKB)          // 0 .. 133120
#define XB0     (4u*CHUNKB)                     // 133120 (aliases GB0/GB1!)
#define XB1     (5u*CHUNKB)                     // 166400
#define GB0F    33280u                          // float idx (byte 133120)
#define GB1F    41984u                          // float idx (byte 167936)
#define BSF     50688u                          // float idx (byte 202752)
#define SMEM_BYTES (202752u + 128u)             // 202880

#define SCL 0.00390625f                         // 1/256 (weights x256)

// persistent scratch (fp16 activations)
__device__ __half g_xh[(size_t)T_LEN*BSZ*HID];
__device__ __half g_h0h[3][BSZ*HID];
__device__ __half g_h1h[3][BSZ*HID];
__device__ unsigned g_cnt;
__device__ unsigned g_gen;

__device__ __forceinline__ float sigm(float x) { return 1.0f / (1.0f + expf(-x)); }

__device__ __forceinline__ void cp16s(uint32_t dst, const void* src) {
    asm volatile("cp.async.cg.shared.global [%0], [%1], 16;" :: "r"(dst), "l"(src));
}
__device__ __forceinline__ void ldsm_x4(uint32_t addr, uint32_t r[4]) {
    asm volatile("ldmatrix.sync.aligned.m8n8.x4.shared.b16 {%0,%1,%2,%3}, [%4];"
        : "=r"(r[0]), "=r"(r[1]), "=r"(r[2]), "=r"(r[3]) : "r"(addr));
}
__device__ __forceinline__ void mma16816(float d[4], const uint32_t a[4],
                                         const uint32_t b[2]) {
    asm volatile("mma.sync.aligned.m16n8k16.row.col.f32.f16.f16.f32 "
        "{%0,%1,%2,%3}, {%4,%5,%6,%7}, {%8,%9}, {%0,%1,%2,%3};"
        : "+f"(d[0]), "+f"(d[1]), "+f"(d[2]), "+f"(d[3])
        : "r"(a[0]), "r"(a[1]), "r"(a[2]), "r"(a[3]), "r"(b[0]), "r"(b[1]));
}
#define CPWAIT(n)  asm volatile("cp.async.wait_group %0;" :: "n"(n) : "memory")
#define CPCOMMIT() asm volatile("cp.async.commit_group;" ::: "memory")

// Grid-wide barrier (proven since R1). All 128 CTAs co-resident.
__device__ __forceinline__ void grid_bar() {
    __threadfence();
    __syncthreads();
    if (threadIdx.x == 0) {
        volatile unsigned* vg = &g_gen;
        unsigned g = *vg;
        unsigned t = atomicAdd(&g_cnt, 1u);
        if (t == NCTA - 1) {
            atomicExch(&g_cnt, 0u);
            __threadfence();
            atomicAdd(&g_gen, 1u);
        } else {
            while (*vg == g) { }
        }
        __threadfence();
    }
    __syncthreads();
}

// Stage a PAIR of 32-row chunks (64 rows x 512 k fp16 = 64KB) into two
// consecutive chunk buffers at bufbyte. All 512 threads, 8x16B each, 1 commit.
__device__ __forceinline__ void stage_pair(uint32_t smb, uint32_t bufbyte,
    const __half* __restrict__ src64, int tid)
{
    #pragma unroll
    for (int j = 0; j < 8; j++) {
        int u = tid + j * 512;
        int b = u >> 6, seg = u & 63;
        cp16s(smb + bufbyte
                  + (uint32_t)((b >> 5) * (int)CHUNKB + (b & 31) * 1040 + seg * 16),
              src64 + (size_t)b * 512 + seg * 8);
    }
    CPCOMMIT();
}

// 64k-window 2-term mma over one chunk (unchanged numerics since R9)
__device__ __forceinline__ void chunk_mma(uint32_t smb, uint32_t bufo, int half_,
    const uint32_t wfm[2][4][4], uint32_t blane, int myks, float d[8][4])
{
    #pragma unroll
    for (int pair = 0; pair < 2; pair++) {
        #pragma unroll
        for (int kb = 0; kb < 4; kb++) {
            uint32_t addr = smb + bufo + (uint32_t)(pair * 16640) + blane
                          + (uint32_t)(myks * 128 + kb * 32);
            uint32_t b4[4];
            ldsm_x4(addr, b4);
            int nt = half_ * 4 + pair * 2;
            mma16816(d[nt],     wfm[0][kb], b4);
            mma16816(d[nt],     wfm[1][kb], b4);
            mma16816(d[nt + 1], wfm[0][kb], b4 + 2);
            mma16816(d[nt + 1], wfm[1][kb], b4 + 2);
        }
    }
}

__device__ __forceinline__ void store_full(float* smf, uint32_t gbF,
    int myks, int lane, const float d[8][4])
{
    float* gb0 = smf + gbF + myks * 1088 + (lane >> 2) * 68 + 2 * (lane & 3);
    #pragma unroll
    for (int nt = 0; nt < 8; nt++) {
        *(float2*)(gb0 + nt * 8)          = make_float2(d[nt][0], d[nt][1]);
        *(float2*)(gb0 + 8 * 68 + nt * 8) = make_float2(d[nt][2], d[nt][3]);
    }
}

__global__ void convert_x(const float* __restrict__ x) {
    size_t i = (size_t)blockIdx.x * blockDim.x + threadIdx.x;   // float4 idx
    float4 v = reinterpret_cast<const float4*>(x)[i];
    __half2* p = reinterpret_cast<__half2*>(g_xh);
    p[2 * i]     = __floats2half2_rn(v.x, v.y);
    p[2 * i + 1] = __floats2half2_rn(v.z, v.w);
}

__global__ void __launch_bounds__(NTHR, 1) lstm_persistent(
    const float* __restrict__ Wxh,  // [2, 2048, 512]
    const float* __restrict__ Whh,  // [2, 2048, 512]
    const float* __restrict__ bxh,  // [2, 2048]
    const float* __restrict__ bhh,  // [2, 2048]
    float* __restrict__ out)        // [T*B*H] ++ hT[2,B,H] ++ cT[2,B,H]
{
    extern __shared__ float smf[];
    char* smc = (char*)smf;
    const uint32_t smb = (uint32_t)__cvta_generic_to_shared(smf);
    const int tid = threadIdx.x;
    const int bj  = blockIdx.x;

    const int wid = tid >> 5, lane = tid & 31, gtid = tid & 255;
    const bool isA = (wid < 8);                  // A = L1, B = L0'
    const int myks = isA ? wid : wid - 8;

    const uint32_t wloff = (uint32_t)(((lane & 7) + ((lane >> 3) & 1) * 8) * 1040
                                     + ((lane >> 4) & 1) * 16);
    const uint32_t blane = (uint32_t)((((lane >> 4) & 1) * 8 + (lane & 7)) * 1040
                                     + ((lane >> 3) & 1) * 16);

    uint32_t wf[2][2][4][4];   // A: [0]=Wx1,[1]=Wh1 ; B: [0]=Wx0,[1]=Wh0
    const int glayer = isA ? 1 : 0;

    // ---- prologue: weights (x256) -> fp16 hi/lo tiles -> reg frags ----
    for (int l = 0; l < 2; l++) {
        for (int idx = tid; idx < 16384; idx += NTHR) {
            int m = idx >> 13, rem = idx & 8191, c = rem >> 9, k = rem & 511;
            const float* bp = m ? Whh : Wxh;
            float w = 256.0f * bp[((size_t)l * 2048 + (size_t)(c >> 2) * 512
                                 + bj * 4 + (c & 3)) * 512 + k];
            __half hi = __float2half(w);
            __half lo = __float2half(w - __half2float(hi));
            *(__half*)(smc + (m * 2 + 0) * 16640 + c * 1040 + k * 2) = hi;
            *(__half*)(smc + (m * 2 + 1) * 16640 + c * 1040 + k * 2) = lo;
        }
        __syncthreads();
        if (glayer == l) {
            #pragma unroll
            for (int m = 0; m < 2; m++)
                #pragma unroll
                for (int p = 0; p < 2; p++)
                    #pragma unroll
                    for (int kb = 0; kb < 4; kb++)
                        ldsm_x4(smb + (uint32_t)((m * 2 + p) * 16640)
                                + wloff + (uint32_t)((myks * 64 + kb * 16) * 2),
                                wf[m][p][kb]);
        }
        __syncthreads();
    }
    if (tid < 32) {
        int l = tid >> 4, j = tid & 15;
        int n = (j >> 2) * 512 + bj * 4 + (j & 3);
        smf[BSF + tid] = bxh[l * 2048 + n] + bhh[l * 2048 + n];
    }
    if (tid < 256)   // zero h1 slot 2 (h1(-1), read at t=0)
        g_h1h[2][bj * 256 + tid] = __float2half(0.f);

    const int ub = gtid >> 2, ucc = tid & 3;     // update role (one per group)
    const int col = bj * 4 + ucc;
    const int hidx = ub * HID + col;
    float c0r = 0.f, c1r = 0.f, h0last = 0.f, h1last = 0.f;
    float d[8][4];

    // ---- prologue B: h0(0) = f(x(0).Wx0 + b0)  (h(-1)=0) ----
    #pragma unroll
    for (int nt = 0; nt < 8; nt++)
        d[nt][0] = d[nt][1] = d[nt][2] = d[nt][3] = 0.f;
    stage_pair(smb, XB0, g_xh, tid);
    CPWAIT(0); __syncthreads();
    if (!isA) {
        chunk_mma(smb, XB0, 0, wf[0], blane, myks, d);
        chunk_mma(smb, XB1, 1, wf[0], blane, myks, d);
        store_full(smf, GB0F, myks, lane, d);
    }
    __syncthreads();
    if (!isA) {
        float gate[4];
        #pragma unroll
        for (int g = 0; g < 4; g++) {
            const float* q = smf + GB0F + (g * 4 + ucc) * 68 + ub;
            float s = 0.f;
            #pragma unroll
            for (int sI = 0; sI < 8; sI++) s += q[sI * 1088];
            gate[g] = s * SCL + smf[BSF + g * 4 + ucc];
        }
        float ig = sigm(gate[0]), fg = sigm(gate[1]);
        float gg = tanhf(gate[2]), og = sigm(gate[3]);
        c0r = fg * c0r + ig * gg;
        h0last = og * tanhf(c0r);
        g_h0h[0][hidx] = __float2half(h0last);
    }
    __syncthreads();
    // pre-stage x(1) (consumed in interval 0, phase 1)
    stage_pair(smb, XB0, g_xh + (size_t)BSZ * HID, tid);
    grid_bar();

    // ---- main loop ----
    for (int t = 0; t < T_LEN; t++) {
        const int s_h0r = t % 3, s_h1r = (t + 2) % 3;
        const int s_h0w = (t + 1) % 3, s_h1w = t % 3;
        const size_t xo2 = (size_t)((t + 2 < T_LEN) ? t + 2 : T_LEN - 1)
                         * (BSZ * HID);

        #pragma unroll
        for (int nt = 0; nt < 8; nt++)
            d[nt][0] = d[nt][1] = d[nt][2] = d[nt][3] = 0.f;

        // stage all h data (x(t+1) already pending from last interval)
        stage_pair(smb, HB(0), g_h0h[s_h0r], tid);   // h0 pair
        stage_pair(smb, HB(2), g_h1h[s_h1r], tid);   // h1 pair
        // pending: x(old), h0, h1

        // phase 1: x + h0 landed
        CPWAIT(1); __syncthreads();
        if (isA) {
            chunk_mma(smb, HB(0), 0, wf[0], blane, myks, d);  // h0_0 . Wx1
            chunk_mma(smb, HB(1), 1, wf[0], blane, myks, d);  // h0_1 . Wx1
        } else {
            chunk_mma(smb, XB0,  0, wf[0], blane, myks, d);   // x_0 . Wx0
            chunk_mma(smb, XB1,  1, wf[0], blane, myks, d);   // x_1 . Wx0
        }
        // phase 2: h1 landed
        CPWAIT(0); __syncthreads();
        if (isA) {
            chunk_mma(smb, HB(2), 0, wf[1], blane, myks, d);  // h1_0 . Wh1
            chunk_mma(smb, HB(3), 1, wf[1], blane, myks, d);  // h1_1 . Wh1
        } else {
            chunk_mma(smb, HB(0), 0, wf[1], blane, myks, d);  // h0_0 . Wh0
            chunk_mma(smb, HB(1), 1, wf[1], blane, myks, d);  // h0_1 . Wh0
        }
        __syncthreads();   // B finished reading XB before GB stores overwrite
        store_full(smf, isA ? GB1F : GB0F, myks, lane, d);
        __syncthreads();

        // concurrent updates
        if (isA) {
            float gate[4];
            #pragma unroll
            for (int g = 0; g < 4; g++) {
                const float* q = smf + GB1F + (g * 4 + ucc) * 68 + ub;
                float s = 0.f;
                #pragma unroll
                for (int sI = 0; sI < 8; sI++) s += q[sI * 1088];
                gate[g] = s * SCL + smf[BSF + 16 + g * 4 + ucc];
            }
            float ig = sigm(gate[0]), fg = sigm(gate[1]);
            float gg = tanhf(gate[2]), og = sigm(gate[3]);
            c1r = fg * c1r + ig * gg;
            h1last = og * tanhf(c1r);
            g_h1h[s_h1w][hidx] = __float2half(h1last);
            out[(size_t)t * (BSZ * HID) + hidx] = h1last;
        } else if (t < T_LEN - 1) {
            float gate[4];
            #pragma unroll
            for (int g = 0; g < 4; g++) {
                const float* q = smf + GB0F + (g * 4 + ucc) * 68 + ub;
                float s = 0.f;
                #pragma unroll
                for (int sI = 0; sI < 8; sI++) s += q[sI * 1088];
                gate[g] = s * SCL + smf[BSF + g * 4 + ucc];
            }
            float ig = sigm(gate[0]), fg = sigm(gate[1]);
            float gg = tanhf(gate[2]), og = sigm(gate[3]);
            c0r = fg * c0r + ig * gg;
            h0last = og * tanhf(c0r);
            g_h0h[s_h0w][hidx] = __float2half(h0last);
        }
        __syncthreads();   // GB reads done before x(t+2) overwrites the alias
        stage_pair(smb, XB0, g_xh + xo2, tid);   // pending into next interval
        grid_bar();
    }
    CPWAIT(0);

    // ---- epilogue: each group owns its states ----
    {
        const size_t OFF = (size_t)T_LEN * BSZ * HID;
        if (!isA) {
            out[OFF +         hidx] = h0last;    // hT layer 0
            out[OFF + 65536 + hidx] = c0r;       // cT layer 0
        } else {
            out[OFF + 32768 + hidx] = h1last;    // hT layer 1
            out[OFF + 98304 + hidx] = c1r;       // cT layer 1
        }
    }
}

extern "C" void kernel_launch(void* const* d_in, const int* in_sizes, int n_in,
                              void* d_out, int out_size) {
    const float* x   = (const float*)d_in[0];
    const float* Wxh = (const float*)d_in[1];
    const float* Whh = (const float*)d_in[2];
    const float* bxh = (const float*)d_in[3];
    const float* bhh = (const float*)d_in[4];
    float* out = (float*)d_out;

    convert_x<<<(T_LEN * BSZ * HID / 4) / 256, 256>>>(x);

    cudaFuncSetAttribute(lstm_persistent,
                         cudaFuncAttributeMaxDynamicSharedMemorySize, SMEM_BYTES);
    lstm_persistent<<<NCTA, NTHR, SMEM_BYTES>>>(Wxh, Whh, bxh, bhh, out);
}

// round 13
// speedup vs baseline: 1.4297x; 1.0776x over previous
#include <cuda_runtime.h>
#include <cuda_fp16.h>
#include <math.h>
#include <stdint.h>

// ---------------------------------------------------------------------------
// 2-layer LSTM, T=512, B=64, H=512, fp32 in/out. Persistent, 128 CTAs x 512.
// R12 (base R11): SINGLE-term fp16 weights (no lo correction) halve MMA work
// and weight regs; B-group holds 3 mats enabling a balanced split:
//   post-bar A (warps 0-7):  h0.Wx1 x2, h1_0.Wh1       -> GB1A (full)
//   post-bar B (warps 8-15): x.Wx0 x2 (ZERO-wait, x resident, hidden under
//                            h0 flight), h0.Wh0 x2 -> GB0, h1_1.Wh1 -> GB1B
// h0 staged jointly (one __syncthreads rendezvous); h1 halves staged
// per-group (named-bar waits only). x staged by B pre-bar. Updates
// concurrent (A->h1+out, B->h0'). x/GB alias. 3-slot rotation, 1 bar/step.
// ---------------------------------------------------------------------------

#define T_LEN 512
#define BSZ   64
#define HID   512
#define NCTA  128
#define NTHR  512

// smem byte layout
#define CHUNKB  33280u
#define HB(i)   ((uint32_t)(i)*CHUNKB)     // h0 pair @0, @33280
#define H1A     (2u*CHUNKB)                // 66560: h1_0 (batch 0-31)
#define H1B     (3u*CHUNKB)                // 99840: h1_1 (batch 32-63)
#define XB0     (4u*CHUNKB)                // 133120 (aliases GB0/GB1A)
#define XB1     (5u*CHUNKB)                // 166400
#define GB0F    33280u                     // float idx (byte 133120) [8][16][68]
#define GB1AF   41984u                     // float idx (byte 167936) [8][16][68]
#define GB1BF   50688u                     // float idx (byte 202752) [8][16][34]
#define BSF     55040u                     // float idx (byte 220160)
#define SMEM_BYTES (220160u + 128u)        // 220288

// persistent scratch (fp16 activations)
__device__ __half g_xh[(size_t)T_LEN*BSZ*HID];
__device__ __half g_h0h[3][BSZ*HID];
__device__ __half g_h1h[3][BSZ*HID];
__device__ unsigned g_cnt;
__device__ unsigned g_gen;

__device__ __forceinline__ float sigm(float x) { return 1.0f / (1.0f + expf(-x)); }

__device__ __forceinline__ void cp16s(uint32_t dst, const void* src) {
    asm volatile("cp.async.cg.shared.global [%0], [%1], 16;" :: "r"(dst), "l"(src));
}
__device__ __forceinline__ void ldsm_x4(uint32_t addr, uint32_t r[4]) {
    asm volatile("ldmatrix.sync.aligned.m8n8.x4.shared.b16 {%0,%1,%2,%3}, [%4];"
        : "=r"(r[0]), "=r"(r[1]), "=r"(r[2]), "=r"(r[3]) : "r"(addr));
}
__device__ __forceinline__ void mma16816(float d[4], const uint32_t a[4],
                                         const uint32_t b[2]) {
    asm volatile("mma.sync.aligned.m16n8k16.row.col.f32.f16.f16.f32 "
        "{%0,%1,%2,%3}, {%4,%5,%6,%7}, {%8,%9}, {%0,%1,%2,%3};"
        : "+f"(d[0]), "+f"(d[1]), "+f"(d[2]), "+f"(d[3])
        : "r"(a[0]), "r"(a[1]), "r"(a[2]), "r"(a[3]), "r"(b[0]), "r"(b[1]));
}
#define CPWAIT(n)  asm volatile("cp.async.wait_group %0;" :: "n"(n) : "memory")
#define CPCOMMIT() asm volatile("cp.async.commit_group;" ::: "memory")
__device__ __forceinline__ void barg(int id) {
    asm volatile("bar.sync %0, 256;" :: "r"(id) : "memory");
}

// Grid-wide barrier (proven since R1). All 128 CTAs co-resident.
__device__ __forceinline__ void grid_bar() {
    __threadfence();
    __syncthreads();
    if (threadIdx.x == 0) {
        volatile unsigned* vg = &g_gen;
        unsigned g = *vg;
        unsigned t = atomicAdd(&g_cnt, 1u);
        if (t == NCTA - 1) {
            atomicExch(&g_cnt, 0u);
            __threadfence();
            atomicAdd(&g_gen, 1u);
        } else {
            while (*vg == g) { }
        }
        __threadfence();
    }
    __syncthreads();
}

// 64-row pair staged by ALL 512 threads (h0)
__device__ __forceinline__ void stage_pair_all(uint32_t smb, uint32_t bufbyte,
    const __half* __restrict__ src64, int tid)
{
    #pragma unroll
    for (int j = 0; j < 8; j++) {
        int u = tid + j * 512;
        int b = u >> 6, seg = u & 63;
        cp16s(smb + bufbyte
                  + (uint32_t)((b >> 5) * (int)CHUNKB + (b & 31) * 1040 + seg * 16),
              src64 + (size_t)b * 512 + seg * 8);
    }
    CPCOMMIT();
}
// 32-row chunk staged by one 256-thread group (h1 halves)
__device__ __forceinline__ void stage_chunk_grp(uint32_t smb, uint32_t bufbyte,
    const __half* __restrict__ src32, int gtid)
{
    #pragma unroll
    for (int j = 0; j < 8; j++) {
        int u = gtid + j * 256;
        int b = u >> 6, seg = u & 63;
        cp16s(smb + bufbyte + (uint32_t)(b * 1040 + seg * 16),
              src32 + (size_t)b * 512 + seg * 8);
    }
    CPCOMMIT();
}
// 64-row pair staged by one 256-thread group (x)
__device__ __forceinline__ void stage_pair_grp(uint32_t smb, uint32_t bufbyte,
    const __half* __restrict__ src64, int gtid)
{
    #pragma unroll
    for (int j = 0; j < 16; j++) {
        int u = gtid + j * 256;
        int b = u >> 6, seg = u & 63;
        cp16s(smb + bufbyte
                  + (uint32_t)((b >> 5) * (int)CHUNKB + (b & 31) * 1040 + seg * 16),
              src64 + (size_t)b * 512 + seg * 8);
    }
    CPCOMMIT();
}

// single-term: 8 ldsm + 16 mma per chunk
__device__ __forceinline__ void chunk_mma1(uint32_t smb, uint32_t bufo, int half_,
    const uint32_t wfm[4][4], uint32_t blane, int myks, float d[8][4])
{
    #pragma unroll
    for (int pair = 0; pair < 2; pair++) {
        #pragma unroll
        for (int kb = 0; kb < 4; kb++) {
            uint32_t addr = smb + bufo + (uint32_t)(pair * 16640) + blane
                          + (uint32_t)(myks * 128 + kb * 32);
            uint32_t b4[4];
            ldsm_x4(addr, b4);
            int nt = half_ * 4 + pair * 2;
            mma16816(d[nt],     wfm[kb], b4);
            mma16816(d[nt + 1], wfm[kb], b4 + 2);
        }
    }
}

__device__ __forceinline__ void store_full(float* smf, uint32_t gbF,
    int myks, int lane, const float d[8][4])
{
    float* gb0 = smf + gbF + myks * 1088 + (lane >> 2) * 68 + 2 * (lane & 3);
    #pragma unroll
    for (int nt = 0; nt < 8; nt++) {
        *(float2*)(gb0 + nt * 8)          = make_float2(d[nt][0], d[nt][1]);
        *(float2*)(gb0 + 8 * 68 + nt * 8) = make_float2(d[nt][2], d[nt][3]);
    }
}
__device__ __forceinline__ void store_half_hi(float* smf, uint32_t gbF,
    int myks, int lane, const float d[8][4])   // nt 4..7 only (batch 32-63)
{
    float* gb0 = smf + gbF + myks * 544 + (lane >> 2) * 34 + 2 * (lane & 3);
    #pragma unroll
    for (int nt = 4; nt < 8; nt++) {
        *(float2*)(gb0 + (nt - 4) * 8)          = make_float2(d[nt][0], d[nt][1]);
        *(float2*)(gb0 + 8 * 34 + (nt - 4) * 8) = make_float2(d[nt][2], d[nt][3]);
    }
}

__global__ void convert_x(const float* __restrict__ x) {
    size_t i = (size_t)blockIdx.x * blockDim.x + threadIdx.x;   // float4 idx
    float4 v = reinterpret_cast<const float4*>(x)[i];
    __half2* p = reinterpret_cast<__half2*>(g_xh);
    p[2 * i]     = __floats2half2_rn(v.x, v.y);
    p[2 * i + 1] = __floats2half2_rn(v.z, v.w);
}

__global__ void __launch_bounds__(NTHR, 1) lstm_persistent(
    const float* __restrict__ Wxh,  // [2, 2048, 512]
    const float* __restrict__ Whh,  // [2, 2048, 512]
    const float* __restrict__ bxh,  // [2, 2048]
    const float* __restrict__ bhh,  // [2, 2048]
    float* __restrict__ out)        // [T*B*H] ++ hT[2,B,H] ++ cT[2,B,H]
{
    extern __shared__ float smf[];
    char* smc = (char*)smf;
    const uint32_t smb = (uint32_t)__cvta_generic_to_shared(smf);
    const int tid = threadIdx.x;
    const int bj  = blockIdx.x;

    const int wid = tid >> 5, lane = tid & 31, gtid = tid & 255;
    const bool isA = (wid < 8);                  // A = L1, B = L0' (+h1_1.Wh1)
    const int myks = isA ? wid : wid - 8;

    const uint32_t wloff = (uint32_t)(((lane & 7) + ((lane >> 3) & 1) * 8) * 1040
                                     + ((lane >> 4) & 1) * 16);
    const uint32_t blane = (uint32_t)((((lane >> 4) & 1) * 8 + (lane & 7)) * 1040
                                     + ((lane >> 3) & 1) * 16);

    // A: [0]=Wx1 [1]=Wh1 ; B: [0]=Wx0 [1]=Wh0 [2]=Wh1   (single-term fp16)
    uint32_t wf[3][4][4];

    // ---- prologue: weights -> fp16 tiles -> reg frags ----
    for (int l = 0; l < 2; l++) {
        for (int idx = tid; idx < 16384; idx += NTHR) {
            int m = idx >> 13, rem = idx & 8191, c = rem >> 9, k = rem & 511;
            const float* bp = m ? Whh : Wxh;
            float w = bp[((size_t)l * 2048 + (size_t)(c >> 2) * 512
                        + bj * 4 + (c & 3)) * 512 + k];
            *(__half*)(smc + m * 16640 + c * 1040 + k * 2) = __float2half(w);
        }
        __syncthreads();
        #pragma unroll
        for (int kb = 0; kb < 4; kb++) {
            uint32_t ko = wloff + (uint32_t)((myks * 64 + kb * 16) * 2);
            if (l == 0 && !isA) {
                ldsm_x4(smb + 0u * 16640u + ko, wf[0][kb]);   // Wx0
                ldsm_x4(smb + 1u * 16640u + ko, wf[1][kb]);   // Wh0
            }
            if (l == 1 && isA) {
                ldsm_x4(smb + 0u * 16640u + ko, wf[0][kb]);   // Wx1
                ldsm_x4(smb + 1u * 16640u + ko, wf[1][kb]);   // Wh1
            }
            if (l == 1 && !isA)
                ldsm_x4(smb + 1u * 16640u + ko, wf[2][kb]);   // Wh1 (for h1_1)
        }
        __syncthreads();
    }
    if (tid < 32) {
        int l = tid >> 4, j = tid & 15;
        int n = (j >> 2) * 512 + bj * 4 + (j & 3);
        smf[BSF + tid] = bxh[l * 2048 + n] + bhh[l * 2048 + n];
    }
    if (tid < 256)   // zero h1 slot 2 (h1(-1), read at t=0)
        g_h1h[2][bj * 256 + tid] = __float2half(0.f);

    const int ub = gtid >> 2, ucc = tid & 3;
    const int col = bj * 4 + ucc;
    const int hidx = ub * HID + col;
    float c0r = 0.f, c1r = 0.f, h0last = 0.f, h1last = 0.f;
    float d[8][4];

    #pragma unroll
    for (int nt = 0; nt < 8; nt++)
        d[nt][0] = d[nt][1] = d[nt][2] = d[nt][3] = 0.f;

    // ---- bootstrap: h0(0) = f(x(0).Wx0 + b0), h(-1)=0 ----
    if (!isA) {
        stage_pair_grp(smb, XB0, g_xh, gtid);
        CPWAIT(0); barg(2);
        chunk_mma1(smb, XB0, 0, wf[0], blane, myks, d);
        chunk_mma1(smb, XB1, 1, wf[0], blane, myks, d);
        barg(2);                         // all B x-reads done (GB0 aliases x)
        store_full(smf, GB0F, myks, lane, d);
    }
    __syncthreads();
    if (!isA) {
        float gate[4];
        #pragma unroll
        for (int g = 0; g < 4; g++) {
            const float* q = smf + GB0F + (g * 4 + ucc) * 68 + ub;
            float s = 0.f;
            #pragma unroll
            for (int sI = 0; sI < 8; sI++) s += q[sI * 1088];
            gate[g] = s + smf[BSF + g * 4 + ucc];
        }
        float ig = sigm(gate[0]), fg = sigm(gate[1]);
        float gg = tanhf(gate[2]), og = sigm(gate[3]);
        c0r = ig * gg;
        h0last = og * tanhf(c0r);
        g_h0h[0][hidx] = __float2half(h0last);
    }
    __syncthreads();
    if (!isA)   // pre-stage x(1) for interval 0
        stage_pair_grp(smb, XB0, g_xh + (size_t)BSZ * HID, gtid);
    grid_bar();

    // ---- main loop: interval t => L1(t) + L0(t+1) ----
    for (int t = 0; t < T_LEN; t++) {
        const int s_h0r = t % 3, s_h1r = (t + 2) % 3;
        const int s_h0w = (t + 1) % 3, s_h1w = t % 3;
        const size_t xo2 = (size_t)((t + 2 < T_LEN) ? t + 2 : T_LEN - 1)
                         * (BSZ * HID);

        #pragma unroll
        for (int nt = 0; nt < 8; nt++)
            d[nt][0] = d[nt][1] = d[nt][2] = d[nt][3] = 0.f;

        // stage: h0 jointly; h1 halves per group
        stage_pair_all(smb, HB(0), g_h0h[s_h0r], tid);
        if (isA) stage_chunk_grp(smb, H1A, g_h1h[s_h1r], gtid);
        else     stage_chunk_grp(smb, H1B, g_h1h[s_h1r] + 32 * 512, gtid);

        if (isA) {
            CPWAIT(1);                         // h0 done (pending: h0, h1_0)
        } else {
            CPWAIT(2);                         // x done (pending: x, h0, h1_1)
            barg(2);
            chunk_mma1(smb, XB0, 0, wf[0], blane, myks, d);   // x_0 . Wx0
            chunk_mma1(smb, XB1, 1, wf[0], blane, myks, d);   // x_1 . Wx0
            CPWAIT(1);                         // h0 done
        }
        __syncthreads();                       // h0 rendezvous (both groups)

        if (isA) {
            chunk_mma1(smb, HB(0), 0, wf[0], blane, myks, d); // h0_0 . Wx1
            chunk_mma1(smb, HB(1), 1, wf[0], blane, myks, d); // h0_1 . Wx1
            CPWAIT(0); barg(1);                // h1_0 landed (A-staged)
            chunk_mma1(smb, H1A, 0, wf[1], blane, myks, d);   // h1_0 . Wh1
            store_full(smf, GB1AF, myks, lane, d);
        } else {
            chunk_mma1(smb, HB(0), 0, wf[1], blane, myks, d); // h0_0 . Wh0
            chunk_mma1(smb, HB(1), 1, wf[1], blane, myks, d); // h0_1 . Wh0
            store_full(smf, GB0F, myks, lane, d);
            #pragma unroll
            for (int nt = 0; nt < 8; nt++)
                d[nt][0] = d[nt][1] = d[nt][2] = d[nt][3] = 0.f;
            CPWAIT(0); barg(2);                // h1_1 landed (B-staged)
            chunk_mma1(smb, H1B, 1, wf[2], blane, myks, d);   // h1_1 . Wh1
            store_half_hi(smf, GB1BF, myks, lane, d);
        }
        __syncthreads();

        // concurrent updates
        if (isA) {
            float gate[4];
            #pragma unroll
            for (int g = 0; g < 4; g++) {
                const float* q = smf + GB1AF + (g * 4 + ucc) * 68 + ub;
                float s = 0.f;
                #pragma unroll
                for (int sI = 0; sI < 8; sI++) s += q[sI * 1088];
                if (ub >= 32) {
                    const float* qb = smf + GB1BF + (g * 4 + ucc) * 34 + (ub - 32);
                    #pragma unroll
                    for (int sI = 0; sI < 8; sI++) s += qb[sI * 544];
                }
                gate[g] = s + smf[BSF + 16 + g * 4 + ucc];
            }
            float ig = sigm(gate[0]), fg = sigm(gate[1]);
            float gg = tanhf(gate[2]), og = sigm(gate[3]);
            c1r = fg * c1r + ig * gg;
            h1last = og * tanhf(c1r);
            g_h1h[s_h1w][hidx] = __float2half(h1last);
            out[(size_t)t * (BSZ * HID) + hidx] = h1last;
        } else if (t < T_LEN - 1) {
            float gate[4];
            #pragma unroll
            for (int g = 0; g < 4; g++) {
                const float* q = smf + GB0F + (g * 4 + ucc) * 68 + ub;
                float s = 0.f;
                #pragma unroll
                for (int sI = 0; sI < 8; sI++) s += q[sI * 1088];
                gate[g] = s + smf[BSF + g * 4 + ucc];
            }
            float ig = sigm(gate[0]), fg = sigm(gate[1]);
            float gg = tanhf(gate[2]), og = sigm(gate[3]);
            c0r = fg * c0r + ig * gg;
            h0last = og * tanhf(c0r);
            g_h0h[s_h0w][hidx] = __float2half(h0last);
        }
        __syncthreads();                       // GB reads done before x overwrite
        if (!isA)
            stage_pair_grp(smb, XB0, g_xh + xo2, gtid);   // pending -> next t
        grid_bar();
    }
    CPWAIT(0);

    // ---- epilogue: each group owns its states ----
    {
        const size_t OFF = (size_t)T_LEN * BSZ * HID;
        if (!isA) {
            out[OFF +         hidx] = h0last;    // hT layer 0
            out[OFF + 65536 + hidx] = c0r;       // cT layer 0
        } else {
            out[OFF + 32768 + hidx] = h1last;    // hT layer 1
            out[OFF + 98304 + hidx] = c1r;       // cT layer 1
        }
    }
}

extern "C" void kernel_launch(void* const* d_in, const int* in_sizes, int n_in,
                              void* d_out, int out_size) {
    const float* x   = (const float*)d_in[0];
    const float* Wxh = (const float*)d_in[1];
    const float* Whh = (const float*)d_in[2];
    const float* bxh = (const float*)d_in[3];
    const float* bhh = (const float*)d_in[4];
    float* out = (float*)d_out;

    convert_x<<<(T_LEN * BSZ * HID / 4) / 256, 256>>>(x);

    cudaFuncSetAttribute(lstm_persistent,
                         cudaFuncAttributeMaxDynamicSharedMemorySize, SMEM_BYTES);
    lstm_persistent<<<NCTA, NTHR, SMEM_BYTES>>>(Wxh, Whh, bxh, bhh, out);
}

// round 14
// speedup vs baseline: 1.7023x; 1.1907x over previous
#include <cuda_runtime.h>
#include <cuda_fp16.h>
#include <math.h>
#include <stdint.h>

// ---------------------------------------------------------------------------
// 2-layer LSTM, T=512, B=64, H=512, fp32 in/out. Persistent, 128 CTAs x 512.
// R13 (base R12): (1) lightweight ticket grid-barrier (release atom +
// acquire poll; no per-thread threadfence/CCTL). (2) x(t+1) staged at
// interval start by B (flight overlaps h0's), removing the prestage and one
// joint sync. (3) MUFU fast sigmoid/tanh in updates.
// Structure: A (warps 0-7): h0.Wx1 x2, h1_0.Wh1 -> GB1A. B (warps 8-15):
// x.Wx0 x2 (waits only x), h0.Wh0 x2 -> GB0, h1_1.Wh1 -> GB1B. Single-term
// fp16 weights in regs, fp32 accum. x/GB alias. 3-slot rotation, 1 bar/step.
// ---------------------------------------------------------------------------

#define T_LEN 512
#define BSZ   64
#define HID   512
#define NCTA  128
#define NTHR  512

// smem byte layout
#define CHUNKB  33280u
#define HB(i)   ((uint32_t)(i)*CHUNKB)     // h0 pair @0, @33280
#define H1A     (2u*CHUNKB)                // 66560: h1_0 (batch 0-31)
#define H1B     (3u*CHUNKB)                // 99840: h1_1 (batch 32-63)
#define XB0     (4u*CHUNKB)                // 133120 (aliases GB0/GB1A)
#define XB1     (5u*CHUNKB)                // 166400
#define GB0F    33280u                     // float idx (byte 133120) [8][16][68]
#define GB1AF   41984u                     // float idx (byte 167936) [8][16][68]
#define GB1BF   50688u                     // float idx (byte 202752) [8][16][34]
#define BSF     55040u                     // float idx (byte 220160)
#define SMEM_BYTES (220160u + 128u)        // 220288

// persistent scratch (fp16 activations)
__device__ __half g_xh[(size_t)T_LEN*BSZ*HID];
__device__ __half g_h0h[3][BSZ*HID];
__device__ __half g_h1h[3][BSZ*HID];
__device__ unsigned g_cnt;                 // monotonic ticket counter

__device__ __forceinline__ float fsigm(float x) {
    return __fdividef(1.0f, 1.0f + __expf(-x));
}
__device__ __forceinline__ float ftanh(float x) {
    float r;
    asm("tanh.approx.f32 %0, %1;" : "=f"(r) : "f"(x));
    return r;
}

__device__ __forceinline__ void cp16s(uint32_t dst, const void* src) {
    asm volatile("cp.async.cg.shared.global [%0], [%1], 16;" :: "r"(dst), "l"(src));
}
__device__ __forceinline__ void ldsm_x4(uint32_t addr, uint32_t r[4]) {
    asm volatile("ldmatrix.sync.aligned.m8n8.x4.shared.b16 {%0,%1,%2,%3}, [%4];"
        : "=r"(r[0]), "=r"(r[1]), "=r"(r[2]), "=r"(r[3]) : "r"(addr));
}
__device__ __forceinline__ void mma16816(float d[4], const uint32_t a[4],
                                         const uint32_t b[2]) {
    asm volatile("mma.sync.aligned.m16n8k16.row.col.f32.f16.f16.f32 "
        "{%0,%1,%2,%3}, {%4,%5,%6,%7}, {%8,%9}, {%0,%1,%2,%3};"
        : "+f"(d[0]), "+f"(d[1]), "+f"(d[2]), "+f"(d[3])
        : "r"(a[0]), "r"(a[1]), "r"(a[2]), "r"(a[3]), "r"(b[0]), "r"(b[1]));
}
#define CPWAIT(n)  asm volatile("cp.async.wait_group %0;" :: "n"(n) : "memory")
#define CPCOMMIT() asm volatile("cp.async.commit_group;" ::: "memory")
__device__ __forceinline__ void barg(int id) {
    asm volatile("bar.sync %0, 256;" :: "r"(id) : "memory");
}

// Lightweight grid barrier: ticket counter, release-arrive / acquire-poll.
// All 128 CTAs co-resident (1 CTA/SM). No per-thread fences, no CCTL.
// Safe because all cross-CTA data consumers use cp.async.cg (L2-direct)
// issued after the acquire; release is cumulative over the block's prior
// stores via the preceding __syncthreads.
__device__ __forceinline__ void grid_bar() {
    __syncthreads();
    if (threadIdx.x == 0) {
        unsigned tk;
        asm volatile("atom.add.release.gpu.u32 %0, [%1], 1;"
                     : "=r"(tk) : "l"(&g_cnt) : "memory");
        unsigned target = (tk & ~127u) + 128u;
        unsigned cur;
        do {
            asm volatile("ld.acquire.gpu.u32 %0, [%1];"
                         : "=r"(cur) : "l"(&g_cnt) : "memory");
        } while (cur < target);
    }
    __syncthreads();
}

// 64-row pair staged by ALL 512 threads (h0)
__device__ __forceinline__ void stage_pair_all(uint32_t smb, uint32_t bufbyte,
    const __half* __restrict__ src64, int tid)
{
    #pragma unroll
    for (int j = 0; j < 8; j++) {
        int u = tid + j * 512;
        int b = u >> 6, seg = u & 63;
        cp16s(smb + bufbyte
                  + (uint32_t)((b >> 5) * (int)CHUNKB + (b & 31) * 1040 + seg * 16),
              src64 + (size_t)b * 512 + seg * 8);
    }
    CPCOMMIT();
}
// 32-row chunk staged by one 256-thread group (h1 halves)
__device__ __forceinline__ void stage_chunk_grp(uint32_t smb, uint32_t bufbyte,
    const __half* __restrict__ src32, int gtid)
{
    #pragma unroll
    for (int j = 0; j < 8; j++) {
        int u = gtid + j * 256;
        int b = u >> 6, seg = u & 63;
        cp16s(smb + bufbyte + (uint32_t)(b * 1040 + seg * 16),
              src32 + (size_t)b * 512 + seg * 8);
    }
    CPCOMMIT();
}
// 64-row pair staged by one 256-thread group (x)
__device__ __forceinline__ void stage_pair_grp(uint32_t smb, uint32_t bufbyte,
    const __half* __restrict__ src64, int gtid)
{
    #pragma unroll
    for (int j = 0; j < 16; j++) {
        int u = gtid + j * 256;
        int b = u >> 6, seg = u & 63;
        cp16s(smb + bufbyte
                  + (uint32_t)((b >> 5) * (int)CHUNKB + (b & 31) * 1040 + seg * 16),
              src64 + (size_t)b * 512 + seg * 8);
    }
    CPCOMMIT();
}

// single-term: 8 ldsm + 16 mma per chunk
__device__ __forceinline__ void chunk_mma1(uint32_t smb, uint32_t bufo, int half_,
    const uint32_t wfm[4][4], uint32_t blane, int myks, float d[8][4])
{
    #pragma unroll
    for (int pair = 0; pair < 2; pair++) {
        #pragma unroll
        for (int kb = 0; kb < 4; kb++) {
            uint32_t addr = smb + bufo + (uint32_t)(pair * 16640) + blane
                          + (uint32_t)(myks * 128 + kb * 32);
            uint32_t b4[4];
            ldsm_x4(addr, b4);
            int nt = half_ * 4 + pair * 2;
            mma16816(d[nt],     wfm[kb], b4);
            mma16816(d[nt + 1], wfm[kb], b4 + 2);
        }
    }
}

__device__ __forceinline__ void store_full(float* smf, uint32_t gbF,
    int myks, int lane, const float d[8][4])
{
    float* gb0 = smf + gbF + myks * 1088 + (lane >> 2) * 68 + 2 * (lane & 3);
    #pragma unroll
    for (int nt = 0; nt < 8; nt++) {
        *(float2*)(gb0 + nt * 8)          = make_float2(d[nt][0], d[nt][1]);
        *(float2*)(gb0 + 8 * 68 + nt * 8) = make_float2(d[nt][2], d[nt][3]);
    }
}
__device__ __forceinline__ void store_half_hi(float* smf, uint32_t gbF,
    int myks, int lane, const float d[8][4])   // nt 4..7 only (batch 32-63)
{
    float* gb0 = smf + gbF + myks * 544 + (lane >> 2) * 34 + 2 * (lane & 3);
    #pragma unroll
    for (int nt = 4; nt < 8; nt++) {
        *(float2*)(gb0 + (nt - 4) * 8)          = make_float2(d[nt][0], d[nt][1]);
        *(float2*)(gb0 + 8 * 34 + (nt - 4) * 8) = make_float2(d[nt][2], d[nt][3]);
    }
}

__global__ void convert_x(const float* __restrict__ x) {
    size_t i = (size_t)blockIdx.x * blockDim.x + threadIdx.x;   // float4 idx
    float4 v = reinterpret_cast<const float4*>(x)[i];
    __half2* p = reinterpret_cast<__half2*>(g_xh);
    p[2 * i]     = __floats2half2_rn(v.x, v.y);
    p[2 * i + 1] = __floats2half2_rn(v.z, v.w);
}

__global__ void __launch_bounds__(NTHR, 1) lstm_persistent(
    const float* __restrict__ Wxh,  // [2, 2048, 512]
    const float* __restrict__ Whh,  // [2, 2048, 512]
    const float* __restrict__ bxh,  // [2, 2048]
    const float* __restrict__ bhh,  // [2, 2048]
    float* __restrict__ out)        // [T*B*H] ++ hT[2,B,H] ++ cT[2,B,H]
{
    extern __shared__ float smf[];
    char* smc = (char*)smf;
    const uint32_t smb = (uint32_t)__cvta_generic_to_shared(smf);
    const int tid = threadIdx.x;
    const int bj  = blockIdx.x;

    const int wid = tid >> 5, lane = tid & 31, gtid = tid & 255;
    const bool isA = (wid < 8);                  // A = L1, B = L0' (+h1_1.Wh1)
    const int myks = isA ? wid : wid - 8;

    const uint32_t wloff = (uint32_t)(((lane & 7) + ((lane >> 3) & 1) * 8) * 1040
                                     + ((lane >> 4) & 1) * 16);
    const uint32_t blane = (uint32_t)((((lane >> 4) & 1) * 8 + (lane & 7)) * 1040
                                     + ((lane >> 3) & 1) * 16);

    // A: [0]=Wx1 [1]=Wh1 ; B: [0]=Wx0 [1]=Wh0 [2]=Wh1   (single-term fp16)
    uint32_t wf[3][4][4];

    // ---- prologue: weights -> fp16 tiles -> reg frags ----
    for (int l = 0; l < 2; l++) {
        for (int idx = tid; idx < 16384; idx += NTHR) {
            int m = idx >> 13, rem = idx & 8191, c = rem >> 9, k = rem & 511;
            const float* bp = m ? Whh : Wxh;
            float w = bp[((size_t)l * 2048 + (size_t)(c >> 2) * 512
                        + bj * 4 + (c & 3)) * 512 + k];
            *(__half*)(smc + m * 16640 + c * 1040 + k * 2) = __float2half(w);
        }
        __syncthreads();
        #pragma unroll
        for (int kb = 0; kb < 4; kb++) {
            uint32_t ko = wloff + (uint32_t)((myks * 64 + kb * 16) * 2);
            if (l == 0 && !isA) {
                ldsm_x4(smb + 0u * 16640u + ko, wf[0][kb]);   // Wx0
                ldsm_x4(smb + 1u * 16640u + ko, wf[1][kb]);   // Wh0
            }
            if (l == 1 && isA) {
                ldsm_x4(smb + 0u * 16640u + ko, wf[0][kb]);   // Wx1
                ldsm_x4(smb + 1u * 16640u + ko, wf[1][kb]);   // Wh1
            }
            if (l == 1 && !isA)
                ldsm_x4(smb + 1u * 16640u + ko, wf[2][kb]);   // Wh1 (for h1_1)
        }
        __syncthreads();
    }
    if (tid < 32) {
        int l = tid >> 4, j = tid & 15;
        int n = (j >> 2) * 512 + bj * 4 + (j & 3);
        smf[BSF + tid] = bxh[l * 2048 + n] + bhh[l * 2048 + n];
    }
    if (tid < 256)   // zero h1 slot 2 (h1(-1), read at t=0)
        g_h1h[2][bj * 256 + tid] = __float2half(0.f);

    const int ub = gtid >> 2, ucc = tid & 3;
    const int col = bj * 4 + ucc;
    const int hidx = ub * HID + col;
    float c0r = 0.f, c1r = 0.f, h0last = 0.f, h1last = 0.f;
    float d[8][4];

    #pragma unroll
    for (int nt = 0; nt < 8; nt++)
        d[nt][0] = d[nt][1] = d[nt][2] = d[nt][3] = 0.f;

    // ---- bootstrap: h0(0) = f(x(0).Wx0 + b0), h(-1)=0 ----
    if (!isA) {
        stage_pair_grp(smb, XB0, g_xh, gtid);
        CPWAIT(0); barg(2);
        chunk_mma1(smb, XB0, 0, wf[0], blane, myks, d);
        chunk_mma1(smb, XB1, 1, wf[0], blane, myks, d);
        barg(2);                         // all B x-reads done (GB0 aliases x)
        store_full(smf, GB0F, myks, lane, d);
    }
    __syncthreads();
    if (!isA) {
        float gate[4];
        #pragma unroll
        for (int g = 0; g < 4; g++) {
            const float* q = smf + GB0F + (g * 4 + ucc) * 68 + ub;
            float s = 0.f;
            #pragma unroll
            for (int sI = 0; sI < 8; sI++) s += q[sI * 1088];
            gate[g] = s + smf[BSF + g * 4 + ucc];
        }
        float ig = fsigm(gate[0]), fg = fsigm(gate[1]);
        float gg = ftanh(gate[2]), og = fsigm(gate[3]);
        c0r = ig * gg;
        h0last = og * ftanh(c0r);
        g_h0h[0][hidx] = __float2half(h0last);
    }
    grid_bar();

    // ---- main loop: interval t => L1(t) + L0(t+1) ----
    for (int t = 0; t < T_LEN; t++) {
        const int s_h0r = t % 3, s_h1r = (t + 2) % 3;
        const int s_h0w = (t + 1) % 3, s_h1w = t % 3;
        const size_t xo1 = (size_t)((t + 1 < T_LEN) ? t + 1 : T_LEN - 1)
                         * (BSZ * HID);

        #pragma unroll
        for (int nt = 0; nt < 8; nt++)
            d[nt][0] = d[nt][1] = d[nt][2] = d[nt][3] = 0.f;

        // stage: B stages x(t+1) first; h0 jointly; h1 halves per group.
        // x flight overlaps h0's; all x reads precede the h0 rendezvous, so
        // GB stores (post-rendezvous) can alias the x buffers.
        if (!isA) stage_pair_grp(smb, XB0, g_xh + xo1, gtid);
        stage_pair_all(smb, HB(0), g_h0h[s_h0r], tid);
        if (isA) stage_chunk_grp(smb, H1A, g_h1h[s_h1r], gtid);
        else     stage_chunk_grp(smb, H1B, g_h1h[s_h1r] + 32 * 512, gtid);

        if (isA) {
            CPWAIT(1);                         // h0 done (pending: h0, h1_0)
        } else {
            CPWAIT(2);                         // x done (pending: x, h0, h1_1)
            barg(2);
            chunk_mma1(smb, XB0, 0, wf[0], blane, myks, d);   // x_0 . Wx0
            chunk_mma1(smb, XB1, 1, wf[0], blane, myks, d);   // x_1 . Wx0
            CPWAIT(1);                         // h0 done
        }
        __syncthreads();                       // h0 rendezvous (both groups)

        if (isA) {
            chunk_mma1(smb, HB(0), 0, wf[0], blane, myks, d); // h0_0 . Wx1
            chunk_mma1(smb, HB(1), 1, wf[0], blane, myks, d); // h0_1 . Wx1
            CPWAIT(0); barg(1);                // h1_0 landed (A-staged)
            chunk_mma1(smb, H1A, 0, wf[1], blane, myks, d);   // h1_0 . Wh1
            store_full(smf, GB1AF, myks, lane, d);
        } else {
            chunk_mma1(smb, HB(0), 0, wf[1], blane, myks, d); // h0_0 . Wh0
            chunk_mma1(smb, HB(1), 1, wf[1], blane, myks, d); // h0_1 . Wh0
            store_full(smf, GB0F, myks, lane, d);
            #pragma unroll
            for (int nt = 0; nt < 8; nt++)
                d[nt][0] = d[nt][1] = d[nt][2] = d[nt][3] = 0.f;
            CPWAIT(0); barg(2);                // h1_1 landed (B-staged)
            chunk_mma1(smb, H1B, 1, wf[2], blane, myks, d);   // h1_1 . Wh1
            store_half_hi(smf, GB1BF, myks, lane, d);
        }
        __syncthreads();

        // concurrent updates
        if (isA) {
            float gate[4];
            #pragma unroll
            for (int g = 0; g < 4; g++) {
                const float* q = smf + GB1AF + (g * 4 + ucc) * 68 + ub;
                float s = 0.f;
                #pragma unroll
                for (int sI = 0; sI < 8; sI++) s += q[sI * 1088];
                if (ub >= 32) {
                    const float* qb = smf + GB1BF + (g * 4 + ucc) * 34 + (ub - 32);
                    #pragma unroll
                    for (int sI = 0; sI < 8; sI++) s += qb[sI * 544];
                }
                gate[g] = s + smf[BSF + 16 + g * 4 + ucc];
            }
            float ig = fsigm(gate[0]), fg = fsigm(gate[1]);
            float gg = ftanh(gate[2]), og = fsigm(gate[3]);
            c1r = fg * c1r + ig * gg;
            h1last = og * ftanh(c1r);
            g_h1h[s_h1w][hidx] = __float2half(h1last);
            out[(size_t)t * (BSZ * HID) + hidx] = h1last;
        } else if (t < T_LEN - 1) {
            float gate[4];
            #pragma unroll
            for (int g = 0; g < 4; g++) {
                const float* q = smf + GB0F + (g * 4 + ucc) * 68 + ub;
                float s = 0.f;
                #pragma unroll
                for (int sI = 0; sI < 8; sI++) s += q[sI * 1088];
                gate[g] = s + smf[BSF + g * 4 + ucc];
            }
            float ig = fsigm(gate[0]), fg = fsigm(gate[1]);
            float gg = ftanh(gate[2]), og = fsigm(gate[3]);
            c0r = fg * c0r + ig * gg;
            h0last = og * ftanh(c0r);
            g_h0h[s_h0w][hidx] = __float2half(h0last);
        }
        grid_bar();
    }
    CPWAIT(0);

    // ---- epilogue: each group owns its states ----
    {
        const size_t OFF = (size_t)T_LEN * BSZ * HID;
        if (!isA) {
            out[OFF +         hidx] = h0last;    // hT layer 0
            out[OFF + 65536 + hidx] = c0r;       // cT layer 0
        } else {
            out[OFF + 32768 + hidx] = h1last;    // hT layer 1
            out[OFF + 98304 + hidx] = c1r;       // cT layer 1
        }
    }
}

extern "C" void kernel_launch(void* const* d_in, const int* in_sizes, int n_in,
                              void* d_out, int out_size) {
    const float* x   = (const float*)d_in[0];
    const float* Wxh = (const float*)d_in[1];
    const float* Whh = (const float*)d_in[2];
    const float* bxh = (const float*)d_in[3];
    const float* bhh = (const float*)d_in[4];
    float* out = (float*)d_out;

    convert_x<<<(T_LEN * BSZ * HID / 4) / 256, 256>>>(x);

    cudaFuncSetAttribute(lstm_persistent,
                         cudaFuncAttributeMaxDynamicSharedMemorySize, SMEM_BYTES);
    lstm_persistent<<<NCTA, NTHR, SMEM_BYTES>>>(Wxh, Whh, bxh, bhh, out);
}

// round 15
// speedup vs baseline: 1.7509x; 1.0286x over previous
#include <cuda_runtime.h>
#include <cuda_fp16.h>
#include <math.h>
#include <stdint.h>

// ---------------------------------------------------------------------------
// 2-layer LSTM, T=512, B=64, H=512, fp32 in/out. Persistent, 128 CTAs x 512.
// R14 (base R13): symmetric 4/4 warp-group split with GROUP-LOCAL epilogues:
//   A (warps 0-7):  h0.Wx1 x2, h1.Wh1 x2 -> GB1 (A stages h1 pair)
//   B (warps 8-15): x.Wx0 x2 (hidden under h0 flight), h0.Wh0 x2 -> GB0
// Each group's update reads only its own partials -> post-MMA sync is a
// named group bar; only joint syncs are the h0 rendezvous + grid bar.
// Ticket grid barrier (release atom + acquire poll), MUFU activations,
// single-term fp16 weights in regs, fp32 accum, x/GB alias, 3-slot h
// rotation, 1 grid bar/step.
// ---------------------------------------------------------------------------

#define T_LEN 512
#define BSZ   64
#define HID   512
#define NCTA  128
#define NTHR  512

// smem byte layout
#define CHUNKB  33280u
#define HB(i)   ((uint32_t)(i)*CHUNKB)     // h0 pair @0, @33280
#define H1P     (2u*CHUNKB)                // 66560: h1 pair (2 chunks)
#define XB0     (4u*CHUNKB)                // 133120 (aliases GB0/GB1)
#define XB1     (5u*CHUNKB)                // 166400
#define GB0F    33280u                     // float idx (byte 133120) [8][16][68]
#define GB1F    41984u                     // float idx (byte 167936) [8][16][68]
#define BSF     50688u                     // float idx (byte 202752)
#define SMEM_BYTES (202752u + 128u)        // 202880

// persistent scratch (fp16 activations)
__device__ __half g_xh[(size_t)T_LEN*BSZ*HID];
__device__ __half g_h0h[3][BSZ*HID];
__device__ __half g_h1h[3][BSZ*HID];
__device__ unsigned g_cnt;                 // monotonic ticket counter

__device__ __forceinline__ float fsigm(float x) {
    return __fdividef(1.0f, 1.0f + __expf(-x));
}
__device__ __forceinline__ float ftanh(float x) {
    float r;
    asm("tanh.approx.f32 %0, %1;" : "=f"(r) : "f"(x));
    return r;
}

__device__ __forceinline__ void cp16s(uint32_t dst, const void* src) {
    asm volatile("cp.async.cg.shared.global [%0], [%1], 16;" :: "r"(dst), "l"(src));
}
__device__ __forceinline__ void ldsm_x4(uint32_t addr, uint32_t r[4]) {
    asm volatile("ldmatrix.sync.aligned.m8n8.x4.shared.b16 {%0,%1,%2,%3}, [%4];"
        : "=r"(r[0]), "=r"(r[1]), "=r"(r[2]), "=r"(r[3]) : "r"(addr));
}
__device__ __forceinline__ void mma16816(float d[4], const uint32_t a[4],
                                         const uint32_t b[2]) {
    asm volatile("mma.sync.aligned.m16n8k16.row.col.f32.f16.f16.f32 "
        "{%0,%1,%2,%3}, {%4,%5,%6,%7}, {%8,%9}, {%0,%1,%2,%3};"
        : "+f"(d[0]), "+f"(d[1]), "+f"(d[2]), "+f"(d[3])
        : "r"(a[0]), "r"(a[1]), "r"(a[2]), "r"(a[3]), "r"(b[0]), "r"(b[1]));
}
#define CPWAIT(n)  asm volatile("cp.async.wait_group %0;" :: "n"(n) : "memory")
#define CPCOMMIT() asm volatile("cp.async.commit_group;" ::: "memory")
__device__ __forceinline__ void barg(int id) {
    asm volatile("bar.sync %0, 256;" :: "r"(id) : "memory");
}

// Lightweight ticket grid barrier (proven in R13). 128 co-resident CTAs.
__device__ __forceinline__ void grid_bar() {
    __syncthreads();
    if (threadIdx.x == 0) {
        unsigned tk;
        asm volatile("atom.add.release.gpu.u32 %0, [%1], 1;"
                     : "=r"(tk) : "l"(&g_cnt) : "memory");
        unsigned target = (tk & ~127u) + 128u;
        unsigned cur;
        do {
            asm volatile("ld.acquire.gpu.u32 %0, [%1];"
                         : "=r"(cur) : "l"(&g_cnt) : "memory");
        } while (cur < target);
    }
    __syncthreads();
}

// 64-row pair staged by ALL 512 threads (h0)
__device__ __forceinline__ void stage_pair_all(uint32_t smb, uint32_t bufbyte,
    const __half* __restrict__ src64, int tid)
{
    #pragma unroll
    for (int j = 0; j < 8; j++) {
        int u = tid + j * 512;
        int b = u >> 6, seg = u & 63;
        cp16s(smb + bufbyte
                  + (uint32_t)((b >> 5) * (int)CHUNKB + (b & 31) * 1040 + seg * 16),
              src64 + (size_t)b * 512 + seg * 8);
    }
    CPCOMMIT();
}
// 64-row pair staged by one 256-thread group (x, h1)
__device__ __forceinline__ void stage_pair_grp(uint32_t smb, uint32_t bufbyte,
    const __half* __restrict__ src64, int gtid)
{
    #pragma unroll
    for (int j = 0; j < 16; j++) {
        int u = gtid + j * 256;
        int b = u >> 6, seg = u & 63;
        cp16s(smb + bufbyte
                  + (uint32_t)((b >> 5) * (int)CHUNKB + (b & 31) * 1040 + seg * 16),
              src64 + (size_t)b * 512 + seg * 8);
    }
    CPCOMMIT();
}

// single-term: 8 ldsm + 16 mma per chunk (64k-window per warp)
__device__ __forceinline__ void chunk_mma1(uint32_t smb, uint32_t bufo, int half_,
    const uint32_t wfm[4][4], uint32_t blane, int myks, float d[8][4])
{
    #pragma unroll
    for (int pair = 0; pair < 2; pair++) {
        #pragma unroll
        for (int kb = 0; kb < 4; kb++) {
            uint32_t addr = smb + bufo + (uint32_t)(pair * 16640) + blane
                          + (uint32_t)(myks * 128 + kb * 32);
            uint32_t b4[4];
            ldsm_x4(addr, b4);
            int nt = half_ * 4 + pair * 2;
            mma16816(d[nt],     wfm[kb], b4);
            mma16816(d[nt + 1], wfm[kb], b4 + 2);
        }
    }
}

__device__ __forceinline__ void store_full(float* smf, uint32_t gbF,
    int myks, int lane, const float d[8][4])
{
    float* gb0 = smf + gbF + myks * 1088 + (lane >> 2) * 68 + 2 * (lane & 3);
    #pragma unroll
    for (int nt = 0; nt < 8; nt++) {
        *(float2*)(gb0 + nt * 8)          = make_float2(d[nt][0], d[nt][1]);
        *(float2*)(gb0 + 8 * 68 + nt * 8) = make_float2(d[nt][2], d[nt][3]);
    }
}

__global__ void convert_x(const float* __restrict__ x) {
    size_t i = (size_t)blockIdx.x * blockDim.x + threadIdx.x;   // float4 idx
    float4 v = reinterpret_cast<const float4*>(x)[i];
    __half2* p = reinterpret_cast<__half2*>(g_xh);
    p[2 * i]     = __floats2half2_rn(v.x, v.y);
    p[2 * i + 1] = __floats2half2_rn(v.z, v.w);
}

__global__ void __launch_bounds__(NTHR, 1) lstm_persistent(
    const float* __restrict__ Wxh,  // [2, 2048, 512]
    const float* __restrict__ Whh,  // [2, 2048, 512]
    const float* __restrict__ bxh,  // [2, 2048]
    const float* __restrict__ bhh,  // [2, 2048]
    float* __restrict__ out)        // [T*B*H] ++ hT[2,B,H] ++ cT[2,B,H]
{
    extern __shared__ float smf[];
    char* smc = (char*)smf;
    const uint32_t smb = (uint32_t)__cvta_generic_to_shared(smf);
    const int tid = threadIdx.x;
    const int bj  = blockIdx.x;

    const int wid = tid >> 5, lane = tid & 31, gtid = tid & 255;
    const bool isA = (wid < 8);                  // A = L1 (h0.Wx1 + h1.Wh1)
    const int myks = isA ? wid : wid - 8;        // B = L0' (x.Wx0 + h0.Wh0)

    const uint32_t wloff = (uint32_t)(((lane & 7) + ((lane >> 3) & 1) * 8) * 1040
                                     + ((lane >> 4) & 1) * 16);
    const uint32_t blane = (uint32_t)((((lane >> 4) & 1) * 8 + (lane & 7)) * 1040
                                     + ((lane >> 3) & 1) * 16);

    // A: [0]=Wx1 [1]=Wh1 ; B: [0]=Wx0 [1]=Wh0   (single-term fp16)
    uint32_t wf[2][4][4];

    // ---- prologue: weights -> fp16 tiles -> reg frags ----
    for (int l = 0; l < 2; l++) {
        for (int idx = tid; idx < 16384; idx += NTHR) {
            int m = idx >> 13, rem = idx & 8191, c = rem >> 9, k = rem & 511;
            const float* bp = m ? Whh : Wxh;
            float w = bp[((size_t)l * 2048 + (size_t)(c >> 2) * 512
                        + bj * 4 + (c & 3)) * 512 + k];
            *(__half*)(smc + m * 16640 + c * 1040 + k * 2) = __float2half(w);
        }
        __syncthreads();
        if ((l == 1) == isA) {
            #pragma unroll
            for (int kb = 0; kb < 4; kb++) {
                uint32_t ko = wloff + (uint32_t)((myks * 64 + kb * 16) * 2);
                ldsm_x4(smb + 0u * 16640u + ko, wf[0][kb]);   // Wx{l}
                ldsm_x4(smb + 1u * 16640u + ko, wf[1][kb]);   // Wh{l}
            }
        }
        __syncthreads();
    }
    if (tid < 32) {
        int l = tid >> 4, j = tid & 15;
        int n = (j >> 2) * 512 + bj * 4 + (j & 3);
        smf[BSF + tid] = bxh[l * 2048 + n] + bhh[l * 2048 + n];
    }
    if (tid < 256)   // zero h1 slot 2 (h1(-1), read at t=0)
        g_h1h[2][bj * 256 + tid] = __float2half(0.f);

    const int ub = gtid >> 2, ucc = tid & 3;
    const int col = bj * 4 + ucc;
    const int hidx = ub * HID + col;
    float c0r = 0.f, c1r = 0.f, h0last = 0.f, h1last = 0.f;
    float d[8][4];

    #pragma unroll
    for (int nt = 0; nt < 8; nt++)
        d[nt][0] = d[nt][1] = d[nt][2] = d[nt][3] = 0.f;

    // ---- bootstrap: h0(0) = f(x(0).Wx0 + b0), h(-1)=0 ----
    if (!isA) {
        stage_pair_grp(smb, XB0, g_xh, gtid);
        CPWAIT(0); barg(2);
        chunk_mma1(smb, XB0, 0, wf[0], blane, myks, d);
        chunk_mma1(smb, XB1, 1, wf[0], blane, myks, d);
        barg(2);                         // all B x-reads done (GB0 aliases x)
        store_full(smf, GB0F, myks, lane, d);
        barg(2);
        float gate[4];
        #pragma unroll
        for (int g = 0; g < 4; g++) {
            const float* q = smf + GB0F + (g * 4 + ucc) * 68 + ub;
            float s = 0.f;
            #pragma unroll
            for (int sI = 0; sI < 8; sI++) s += q[sI * 1088];
            gate[g] = s + smf[BSF + g * 4 + ucc];
        }
        float ig = fsigm(gate[0]), fg = fsigm(gate[1]);
        float gg = ftanh(gate[2]), og = fsigm(gate[3]);
        c0r = ig * gg;
        h0last = og * ftanh(c0r);
        g_h0h[0][hidx] = __float2half(h0last);
    }
    grid_bar();

    // ---- main loop: interval t => L1(t) (A) + L0(t+1) (B) ----
    for (int t = 0; t < T_LEN; t++) {
        const int s_h0r = t % 3, s_h1r = (t + 2) % 3;
        const int s_h0w = (t + 1) % 3, s_h1w = t % 3;
        const size_t xo1 = (size_t)((t + 1 < T_LEN) ? t + 1 : T_LEN - 1)
                         * (BSZ * HID);

        #pragma unroll
        for (int nt = 0; nt < 8; nt++)
            d[nt][0] = d[nt][1] = d[nt][2] = d[nt][3] = 0.f;

        // staging. Commit order per thread: A = [h0, h1], B = [x, h0].
        if (!isA) stage_pair_grp(smb, XB0, g_xh + xo1, gtid);
        stage_pair_all(smb, HB(0), g_h0h[s_h0r], tid);
        if (isA)  stage_pair_grp(smb, H1P, g_h1h[s_h1r], gtid);

        if (isA) {
            CPWAIT(1);                         // own h0 part done (h1 pending)
        } else {
            CPWAIT(1);                         // x done (h0 pending)
            barg(2);
            chunk_mma1(smb, XB0, 0, wf[0], blane, myks, d);   // x_0 . Wx0
            chunk_mma1(smb, XB1, 1, wf[0], blane, myks, d);   // x_1 . Wx0
            CPWAIT(0);                         // own h0 part done
        }
        __syncthreads();                       // h0 rendezvous (joint)

        if (isA) {
            chunk_mma1(smb, HB(0), 0, wf[0], blane, myks, d); // h0_0 . Wx1
            chunk_mma1(smb, HB(1), 1, wf[0], blane, myks, d); // h0_1 . Wx1
            CPWAIT(0); barg(1);                // h1 pair landed (A-staged)
            chunk_mma1(smb, H1P,            0, wf[1], blane, myks, d); // h1_0.Wh1
            chunk_mma1(smb, H1P + CHUNKB,   1, wf[1], blane, myks, d); // h1_1.Wh1
            store_full(smf, GB1F, myks, lane, d);
            barg(1);                           // group-local epilogue sync
            // ---- A update: h1(t) ----
            float gate[4];
            #pragma unroll
            for (int g = 0; g < 4; g++) {
                const float* q = smf + GB1F + (g * 4 + ucc) * 68 + ub;
                float s = 0.f;
                #pragma unroll
                for (int sI = 0; sI < 8; sI++) s += q[sI * 1088];
                gate[g] = s + smf[BSF + 16 + g * 4 + ucc];
            }
            float ig = fsigm(gate[0]), fg = fsigm(gate[1]);
            float gg = ftanh(gate[2]), og = fsigm(gate[3]);
            c1r = fg * c1r + ig * gg;
            h1last = og * ftanh(c1r);
            g_h1h[s_h1w][hidx] = __float2half(h1last);
            out[(size_t)t * (BSZ * HID) + hidx] = h1last;
        } else {
            chunk_mma1(smb, HB(0), 0, wf[1], blane, myks, d); // h0_0 . Wh0
            chunk_mma1(smb, HB(1), 1, wf[1], blane, myks, d); // h0_1 . Wh0
            store_full(smf, GB0F, myks, lane, d);
            barg(2);                           // group-local epilogue sync
            // ---- B update: h0(t+1) ----
            if (t < T_LEN - 1) {
                float gate[4];
                #pragma unroll
                for (int g = 0; g < 4; g++) {
                    const float* q = smf + GB0F + (g * 4 + ucc) * 68 + ub;
                    float s = 0.f;
                    #pragma unroll
                    for (int sI = 0; sI < 8; sI++) s += q[sI * 1088];
                    gate[g] = s + smf[BSF + g * 4 + ucc];
                }
                float ig = fsigm(gate[0]), fg = fsigm(gate[1]);
                float gg = ftanh(gate[2]), og = fsigm(gate[3]);
                c0r = fg * c0r + ig * gg;
                h0last = og * ftanh(c0r);
                g_h0h[s_h0w][hidx] = __float2half(h0last);
            }
        }
        grid_bar();
    }
    CPWAIT(0);

    // ---- epilogue: each group owns its states ----
    {
        const size_t OFF = (size_t)T_LEN * BSZ * HID;
        if (!isA) {
            out[OFF +         hidx] = h0last;    // hT layer 0
            out[OFF + 65536 + hidx] = c0r;       // cT layer 0
        } else {
            out[OFF + 32768 + hidx] = h1last;    // hT layer 1
            out[OFF + 98304 + hidx] = c1r;       // cT layer 1
        }
    }
}

extern "C" void kernel_launch(void* const* d_in, const int* in_sizes, int n_in,
                              void* d_out, int out_size) {
    const float* x   = (const float*)d_in[0];
    const float* Wxh = (const float*)d_in[1];
    const float* Whh = (const float*)d_in[2];
    const float* bxh = (const float*)d_in[3];
    const float* bhh = (const float*)d_in[4];
    float* out = (float*)d_out;

    convert_x<<<(T_LEN * BSZ * HID / 4) / 256, 256>>>(x);

    cudaFuncSetAttribute(lstm_persistent,
                         cudaFuncAttributeMaxDynamicSharedMemorySize, SMEM_BYTES);
    lstm_persistent<<<NCTA, NTHR, SMEM_BYTES>>>(Wxh, Whh, bxh, bhh, out);
}